// round 5
// baseline (speedup 1.0000x reference)
#include <cuda_runtime.h>
#include <cstdint>
#include <math.h>

// Problem constants (fixed by the reference's setup_inputs)
#define D 256
#define FFD 1024
#define NH 8
#define NL 4
#define NP 4
#define HD 32
#define BATCH 8
#define LQ 1024
#define NQROWS (BATCH * LQ)      // 8192
#define LIN 13294
#define NVROWS (BATCH * LIN)     // 106352

__constant__ int c_H[NL]  = {100, 50, 25, 13};
__constant__ int c_W[NL]  = {100, 50, 25, 13};
__constant__ int c_ST[NL] = {0, 10000, 12500, 13125};

// ---------------- scratch (static device memory; no allocations) ----------
__device__ float g_q[NQROWS * D];
__device__ float g_off[NQROWS * D];
__device__ float g_aw[NQROWS * 128];
__device__ float g_val[(size_t)NVROWS * D];
__device__ float g_msda[NQROWS * D];
__device__ float g_proj[NQROWS * D];
__device__ float g_t1[NQROWS * D];
__device__ float g_t1r[NQROWS * D];
__device__ float g_t2[NQROWS * D];
__device__ float g_t2r[NQROWS * D];
__device__ float g_qkv[NQROWS * 3 * D];
__device__ float g_o[NQROWS * D];
__device__ float g_ffn[NQROWS * FFD];
__device__ float g_wr[1015808];                   // tf32-rounded weights

// ---------------- helpers --------------------------------------------------
__device__ __forceinline__ void cp16(uint32_t dst, const float* src, int sz) {
    asm volatile("cp.async.cg.shared.global [%0], [%1], 16, %2;"
                 :: "r"(dst), "l"(src), "r"(sz));
}
__device__ __forceinline__ uint32_t f2tf32(float x) {
    uint32_t r;
    asm("cvt.rna.tf32.f32 %0, %1;" : "=r"(r) : "f"(x));
    return r;
}
__device__ __forceinline__ float rnd_tf32(float x) {
    return __uint_as_float(f2tf32(x));
}
__device__ __forceinline__ void mma_tf32(float* d, const uint32_t* a, const uint32_t* b) {
    asm volatile(
        "mma.sync.aligned.m16n8k8.row.col.f32.tf32.tf32.f32 "
        "{%0,%1,%2,%3}, {%4,%5,%6,%7}, {%8,%9}, {%0,%1,%2,%3};"
        : "+f"(d[0]), "+f"(d[1]), "+f"(d[2]), "+f"(d[3])
        : "r"(a[0]), "r"(a[1]), "r"(a[2]), "r"(a[3]), "r"(b[0]), "r"(b[1]));
}

// ---------------- rounding prepass ----------------------------------------
__global__ void round4_kernel(const float* __restrict__ in, float* __restrict__ out, int n4) {
    int i = blockIdx.x * blockDim.x + threadIdx.x;
    if (i < n4) {
        float4 f = ((const float4*)in)[i];
        f.x = rnd_tf32(f.x); f.y = rnd_tf32(f.y);
        f.z = rnd_tf32(f.z); f.w = rnd_tf32(f.w);
        ((float4*)out)[i] = f;
    }
}

// ---------------- elementwise add (rounded): q = tgt + query_pos ----------
__global__ void add_kernel(const float* __restrict__ a, const float* __restrict__ b,
                           float* __restrict__ out, int n) {
    int i = blockIdx.x * blockDim.x + threadIdx.x;
    if (i < n) out[i] = rnd_tf32(a[i] + b[i]);
}

// ======================= tf32 MMA GEMM =====================================
// C[M,N] = (A[M,K] @ B[N,K]^T) + bias, optional relu, optional rounded output.
// CVTA=1: A values are raw fp32 and get cvt.rna per fragment.
// CVTA=0: A values pre-rounded to tf32; raw bits used directly.
// B always pre-rounded. Requires N % 128 == 0, K % 16 == 0; M guarded.
#define SROW 20

template <int CVTA>
__global__ __launch_bounds__(256, 2) void mma_gemm_kernel(
    const float* __restrict__ A, int lda,
    const float* __restrict__ Bw, int ldb,
    const float* __restrict__ bias,
    float* __restrict__ C, int ldc,
    int M, int K, int relu, int rnd)
{
    __shared__ float As[2][128][SROW];
    __shared__ float Bs[2][128][SROW];

    const int tid = threadIdx.x;
    const int wid = tid >> 5, lane = tid & 31;
    const int warpM = wid & 1, warpN = wid >> 1;
    const int row0 = blockIdx.y * 128, col0 = blockIdx.x * 128;

    const uint32_t sAbase = (uint32_t)__cvta_generic_to_shared(&As[0][0][0]);
    const uint32_t sBbase = (uint32_t)__cvta_generic_to_shared(&Bs[0][0][0]);

    float acc[4][4][4];
#pragma unroll
    for (int mt = 0; mt < 4; mt++)
#pragma unroll
        for (int nt = 0; nt < 4; nt++)
#pragma unroll
            for (int r = 0; r < 4; r++) acc[mt][nt][r] = 0.f;

    const int lr = tid >> 2;
    const int kq = (tid & 3) * 4;

    {
#pragma unroll
        for (int i = 0; i < 2; i++) {
            int r = lr + i * 64;
            int gr = row0 + r;
            const float* gp = A + (size_t)(gr < M ? gr : 0) * lda + kq;
            cp16(sAbase + (uint32_t)((r * SROW + kq) * 4), gp, gr < M ? 16 : 0);
        }
#pragma unroll
        for (int i = 0; i < 2; i++) {
            int r = lr + i * 64;
            const float* gp = Bw + (size_t)(col0 + r) * ldb + kq;
            cp16(sBbase + (uint32_t)((r * SROW + kq) * 4), gp, 16);
        }
        asm volatile("cp.async.commit_group;");
    }

    const int KT = K >> 4;
    for (int kt = 0; kt < KT; kt++) {
        const int buf = kt & 1;
        if (kt + 1 < KT) {
            const int nb = buf ^ 1;
            const int k0 = (kt + 1) << 4;
            const uint32_t offS = (uint32_t)(nb * 128 * SROW * 4);
#pragma unroll
            for (int i = 0; i < 2; i++) {
                int r = lr + i * 64;
                int gr = row0 + r;
                const float* gp = A + (size_t)(gr < M ? gr : 0) * lda + k0 + kq;
                cp16(sAbase + offS + (uint32_t)((r * SROW + kq) * 4), gp, gr < M ? 16 : 0);
            }
#pragma unroll
            for (int i = 0; i < 2; i++) {
                int r = lr + i * 64;
                const float* gp = Bw + (size_t)(col0 + r) * ldb + k0 + kq;
                cp16(sBbase + offS + (uint32_t)((r * SROW + kq) * 4), gp, 16);
            }
            asm volatile("cp.async.commit_group;");
            asm volatile("cp.async.wait_group 1;");
        } else {
            asm volatile("cp.async.wait_group 0;");
        }
        __syncthreads();

#pragma unroll
        for (int ks = 0; ks < 2; ks++) {
            uint32_t af[4][4], bf[4][2];
            const int kc = ks * 8 + (lane & 3);
            const int g4 = lane >> 2;
#pragma unroll
            for (int mt = 0; mt < 4; mt++) {
                const int r = warpM * 64 + mt * 16 + g4;
                if (CVTA) {
                    af[mt][0] = f2tf32(As[buf][r][kc]);
                    af[mt][1] = f2tf32(As[buf][r + 8][kc]);
                    af[mt][2] = f2tf32(As[buf][r][kc + 4]);
                    af[mt][3] = f2tf32(As[buf][r + 8][kc + 4]);
                } else {
                    af[mt][0] = __float_as_uint(As[buf][r][kc]);
                    af[mt][1] = __float_as_uint(As[buf][r + 8][kc]);
                    af[mt][2] = __float_as_uint(As[buf][r][kc + 4]);
                    af[mt][3] = __float_as_uint(As[buf][r + 8][kc + 4]);
                }
            }
#pragma unroll
            for (int nt = 0; nt < 4; nt++) {
                const int n = warpN * 32 + nt * 8 + g4;
                bf[nt][0] = __float_as_uint(Bs[buf][n][kc]);
                bf[nt][1] = __float_as_uint(Bs[buf][n][kc + 4]);
            }
#pragma unroll
            for (int mt = 0; mt < 4; mt++)
#pragma unroll
                for (int nt = 0; nt < 4; nt++)
                    mma_tf32(acc[mt][nt], af[mt], bf[nt]);
        }
        __syncthreads();
    }

    const int g4 = lane >> 2;
    const int c2 = (lane & 3) * 2;
#pragma unroll
    for (int mt = 0; mt < 4; mt++) {
        const int r = row0 + warpM * 64 + mt * 16 + g4;
#pragma unroll
        for (int nt = 0; nt < 4; nt++) {
            const int cc = col0 + warpN * 32 + nt * 8 + c2;
            float b0 = 0.f, b1 = 0.f;
            if (bias) { b0 = bias[cc]; b1 = bias[cc + 1]; }
            float v0 = acc[mt][nt][0] + b0;
            float v1 = acc[mt][nt][1] + b1;
            float v2 = acc[mt][nt][2] + b0;
            float v3 = acc[mt][nt][3] + b1;
            if (relu) {
                v0 = fmaxf(v0, 0.f); v1 = fmaxf(v1, 0.f);
                v2 = fmaxf(v2, 0.f); v3 = fmaxf(v3, 0.f);
            }
            if (rnd) {
                v0 = rnd_tf32(v0); v1 = rnd_tf32(v1);
                v2 = rnd_tf32(v2); v3 = rnd_tf32(v3);
            }
            if (r < M)     *(float2*)(C + (size_t)r * ldc + cc)       = make_float2(v0, v1);
            if (r + 8 < M) *(float2*)(C + (size_t)(r + 8) * ldc + cc) = make_float2(v2, v3);
        }
    }
}

// ======================= flash attention ===================================
// Per block: one (b,h) and a 64-query tile. 128 threads = 4 warps (2x2).
__global__ __launch_bounds__(128) void flash_attn_kernel(
    const float* __restrict__ qkv, float* __restrict__ o)
{
    __shared__ float Qs[64][36];       // reused as P (tf32 bits) after preload
    __shared__ float Ks[64][36];
    __shared__ float Vs[64][40];
    __shared__ float rm[2][64];
    __shared__ float rl[2][64];

    const int bh = blockIdx.y;
    const int b = bh >> 3, h = bh & 7;
    const int q0 = blockIdx.x * 64;
    const int tid = threadIdx.x;
    const int wid = tid >> 5, lane = tid & 31;
    const int warpM = wid & 1, warpN = wid >> 1;
    const int g4 = lane >> 2, l3 = lane & 3;
    const float scale = 0.17677669529663687f;   // 1/sqrt(32)

    const uint32_t sK = (uint32_t)__cvta_generic_to_shared(&Ks[0][0]);
    const uint32_t sV = (uint32_t)__cvta_generic_to_shared(&Vs[0][0]);

#pragma unroll
    for (int i = 0; i < 4; i++) {
        int idx = tid + i * 128;
        int r = idx >> 3, cq = (idx & 7) * 4;
        float4 f = *(const float4*)(qkv + ((size_t)(b * LQ + q0 + r)) * 768 + h * 32 + cq);
        Qs[r][cq + 0] = f.x; Qs[r][cq + 1] = f.y;
        Qs[r][cq + 2] = f.z; Qs[r][cq + 3] = f.w;
    }
    __syncthreads();

    uint32_t qf[2][4][4];
#pragma unroll
    for (int mt = 0; mt < 2; mt++) {
        const int r0 = warpM * 32 + mt * 16 + g4;
#pragma unroll
        for (int ks = 0; ks < 4; ks++) {
            const int k = ks * 8 + l3;
            qf[mt][ks][0] = f2tf32(Qs[r0][k] * scale);
            qf[mt][ks][1] = f2tf32(Qs[r0 + 8][k] * scale);
            qf[mt][ks][2] = f2tf32(Qs[r0][k + 4] * scale);
            qf[mt][ks][3] = f2tf32(Qs[r0 + 8][k + 4] * scale);
        }
    }
    __syncthreads();
    uint32_t* Ps = (uint32_t*)&Qs[0][0];

    float Oa[2][2][4];
#pragma unroll
    for (int mt = 0; mt < 2; mt++)
#pragma unroll
        for (int nt = 0; nt < 2; nt++)
#pragma unroll
            for (int r = 0; r < 4; r++) Oa[mt][nt][r] = 0.f;
    float m_r[2][2], l_r[2][2];
#pragma unroll
    for (int mt = 0; mt < 2; mt++) {
        m_r[mt][0] = -1e30f; m_r[mt][1] = -1e30f;
        l_r[mt][0] = 0.f;    l_r[mt][1] = 0.f;
    }

    for (int kt = 0; kt < 16; kt++) {
        const int k0 = kt * 64;
#pragma unroll
        for (int i = 0; i < 4; i++) {
            int idx = tid + i * 128;
            int r = idx >> 3, cq = (idx & 7) * 4;
            const float* kp = qkv + ((size_t)(b * LQ + k0 + r)) * 768 + 256 + h * 32 + cq;
            cp16(sK + (uint32_t)((r * 36 + cq) * 4), kp, 16);
            const float* vp = qkv + ((size_t)(b * LQ + k0 + r)) * 768 + 512 + h * 32 + cq;
            cp16(sV + (uint32_t)((r * 40 + cq) * 4), vp, 16);
        }
        asm volatile("cp.async.commit_group;");
        asm volatile("cp.async.wait_group 0;");
        __syncthreads();

        float Sa[2][4][4];
#pragma unroll
        for (int mt = 0; mt < 2; mt++)
#pragma unroll
            for (int nt = 0; nt < 4; nt++)
#pragma unroll
                for (int r = 0; r < 4; r++) Sa[mt][nt][r] = 0.f;
#pragma unroll
        for (int ks = 0; ks < 4; ks++) {
            uint32_t bf[4][2];
            const int k = ks * 8 + l3;
#pragma unroll
            for (int nt = 0; nt < 4; nt++) {
                const int n = warpN * 32 + nt * 8 + g4;
                bf[nt][0] = f2tf32(Ks[n][k]);
                bf[nt][1] = f2tf32(Ks[n][k + 4]);
            }
#pragma unroll
            for (int mt = 0; mt < 2; mt++)
#pragma unroll
                for (int nt = 0; nt < 4; nt++)
                    mma_tf32(Sa[mt][nt], qf[mt][ks], bf[nt]);
        }

#pragma unroll
        for (int mt = 0; mt < 2; mt++) {
            float m0 = -1e30f, m1 = -1e30f;
#pragma unroll
            for (int nt = 0; nt < 4; nt++) {
                m0 = fmaxf(m0, fmaxf(Sa[mt][nt][0], Sa[mt][nt][1]));
                m1 = fmaxf(m1, fmaxf(Sa[mt][nt][2], Sa[mt][nt][3]));
            }
            m0 = fmaxf(m0, __shfl_xor_sync(0xffffffffu, m0, 1));
            m0 = fmaxf(m0, __shfl_xor_sync(0xffffffffu, m0, 2));
            m1 = fmaxf(m1, __shfl_xor_sync(0xffffffffu, m1, 1));
            m1 = fmaxf(m1, __shfl_xor_sync(0xffffffffu, m1, 2));
            if (l3 == 0) {
                rm[warpN][warpM * 32 + mt * 16 + g4] = m0;
                rm[warpN][warpM * 32 + mt * 16 + g4 + 8] = m1;
            }
        }
        __syncthreads();

        float mn[2][2];
#pragma unroll
        for (int mt = 0; mt < 2; mt++) {
            const int r0 = warpM * 32 + mt * 16 + g4;
            mn[mt][0] = fmaxf(m_r[mt][0], fmaxf(rm[0][r0], rm[1][r0]));
            mn[mt][1] = fmaxf(m_r[mt][1], fmaxf(rm[0][r0 + 8], rm[1][r0 + 8]));
            float s0 = 0.f, s1 = 0.f;
#pragma unroll
            for (int nt = 0; nt < 4; nt++) {
                float p0 = __expf(Sa[mt][nt][0] - mn[mt][0]);
                float p1 = __expf(Sa[mt][nt][1] - mn[mt][0]);
                float p2 = __expf(Sa[mt][nt][2] - mn[mt][1]);
                float p3 = __expf(Sa[mt][nt][3] - mn[mt][1]);
                s0 += p0 + p1; s1 += p2 + p3;
                const int cc = warpN * 32 + nt * 8 + l3 * 2;
                Ps[r0 * 36 + cc]           = f2tf32(p0);
                Ps[r0 * 36 + cc + 1]       = f2tf32(p1);
                Ps[(r0 + 8) * 36 + cc]     = f2tf32(p2);
                Ps[(r0 + 8) * 36 + cc + 1] = f2tf32(p3);
            }
            s0 += __shfl_xor_sync(0xffffffffu, s0, 1);
            s0 += __shfl_xor_sync(0xffffffffu, s0, 2);
            s1 += __shfl_xor_sync(0xffffffffu, s1, 1);
            s1 += __shfl_xor_sync(0xffffffffu, s1, 2);
            if (l3 == 0) {
                rl[warpN][r0] = s0;
                rl[warpN][r0 + 8] = s1;
            }
        }
        __syncthreads();

#pragma unroll
        for (int mt = 0; mt < 2; mt++) {
            const int r0 = warpM * 32 + mt * 16 + g4;
            const float a0 = __expf(m_r[mt][0] - mn[mt][0]);
            const float a1 = __expf(m_r[mt][1] - mn[mt][1]);
            l_r[mt][0] = l_r[mt][0] * a0 + rl[0][r0] + rl[1][r0];
            l_r[mt][1] = l_r[mt][1] * a1 + rl[0][r0 + 8] + rl[1][r0 + 8];
            m_r[mt][0] = mn[mt][0];
            m_r[mt][1] = mn[mt][1];
#pragma unroll
            for (int nt = 0; nt < 2; nt++) {
                Oa[mt][nt][0] *= a0; Oa[mt][nt][1] *= a0;
                Oa[mt][nt][2] *= a1; Oa[mt][nt][3] *= a1;
            }
        }

#pragma unroll
        for (int kk = 0; kk < 8; kk++) {
            const int k = kk * 8 + l3;
            uint32_t bf[2][2];
#pragma unroll
            for (int nt = 0; nt < 2; nt++) {
                const int n = warpN * 16 + nt * 8 + g4;
                bf[nt][0] = f2tf32(Vs[k][n]);
                bf[nt][1] = f2tf32(Vs[k + 4][n]);
            }
#pragma unroll
            for (int mt = 0; mt < 2; mt++) {
                const int r0 = warpM * 32 + mt * 16 + g4;
                uint32_t af[4];
                af[0] = Ps[r0 * 36 + k];
                af[1] = Ps[(r0 + 8) * 36 + k];
                af[2] = Ps[r0 * 36 + k + 4];
                af[3] = Ps[(r0 + 8) * 36 + k + 4];
#pragma unroll
                for (int nt = 0; nt < 2; nt++)
                    mma_tf32(Oa[mt][nt], af, bf[nt]);
            }
        }
        __syncthreads();
    }

    const int c2 = l3 * 2;
#pragma unroll
    for (int mt = 0; mt < 2; mt++) {
        const int r0 = q0 + warpM * 32 + mt * 16 + g4;
        const float i0 = 1.f / l_r[mt][0];
        const float i1 = 1.f / l_r[mt][1];
#pragma unroll
        for (int nt = 0; nt < 2; nt++) {
            const int cc = h * 32 + warpN * 16 + nt * 8 + c2;
            *(float2*)(o + ((size_t)(b * LQ + r0)) * D + cc) =
                make_float2(rnd_tf32(Oa[mt][nt][0] * i0), rnd_tf32(Oa[mt][nt][1] * i0));
            *(float2*)(o + ((size_t)(b * LQ + r0 + 8)) * D + cc) =
                make_float2(rnd_tf32(Oa[mt][nt][2] * i1), rnd_tf32(Oa[mt][nt][3] * i1));
        }
    }
}

// ---------------- MSDA sampling kernel ------------------------------------
__global__ __launch_bounds__(256) void msda_kernel(
    const float* __restrict__ off, const float* __restrict__ awraw,
    const float* __restrict__ ref, const float* __restrict__ val,
    float* __restrict__ out)
{
    const int row = blockIdx.x;            // b*LQ + lq
    const int b = row >> 10;
    const int t = threadIdx.x;
    const int h = t >> 5;
    const int c = t & 31;

    const float* awp = awraw + (size_t)row * 128 + h * 16;
    float w[16];
    float mx = -1e30f;
#pragma unroll
    for (int i = 0; i < 16; i++) { w[i] = awp[i]; mx = fmaxf(mx, w[i]); }
    float s = 0.f;
#pragma unroll
    for (int i = 0; i < 16; i++) { w[i] = expf(w[i] - mx); s += w[i]; }
    const float inv = 1.f / s;

    const float* offp = off + (size_t)row * 256 + h * 32;   // [NL][NP][2]
    const float* refp = ref + (size_t)row * (NL * 2);

    float acc = 0.f;
#pragma unroll
    for (int l = 0; l < NL; l++) {
        const float rx = refp[l * 2 + 0];
        const float ry = refp[l * 2 + 1];
        const int H = c_H[l], W = c_W[l];
        const float fW = (float)W, fH = (float)H;
        const float* vbase = val + ((size_t)b * LIN + c_ST[l]) * D + h * HD + c;
#pragma unroll
        for (int p = 0; p < NP; p++) {
            const float ox = offp[(l * NP + p) * 2 + 0];
            const float oy = offp[(l * NP + p) * 2 + 1];
            const float x = (rx + ox / fW) * fW - 0.5f;
            const float y = (ry + oy / fH) * fH - 0.5f;
            const float x0f = floorf(x), y0f = floorf(y);
            const float wx = x - x0f, wy = y - y0f;
            const int x0 = (int)x0f, y0 = (int)y0f;
            float samp = 0.f;
            if (y0 >= 0 && y0 < H) {
                if (x0 >= 0 && x0 < W)
                    samp += (1.f - wy) * (1.f - wx) * vbase[(size_t)(y0 * W + x0) * D];
                if (x0 + 1 >= 0 && x0 + 1 < W)
                    samp += (1.f - wy) * wx * vbase[(size_t)(y0 * W + x0 + 1) * D];
            }
            if (y0 + 1 >= 0 && y0 + 1 < H) {
                if (x0 >= 0 && x0 < W)
                    samp += wy * (1.f - wx) * vbase[(size_t)((y0 + 1) * W + x0) * D];
                if (x0 + 1 >= 0 && x0 + 1 < W)
                    samp += wy * wx * vbase[(size_t)((y0 + 1) * W + x0 + 1) * D];
            }
            acc = fmaf(w[l * NP + p] * inv, samp, acc);
        }
    }
    out[(size_t)row * D + h * HD + c] = rnd_tf32(acc);
}

// ---------------- residual + LayerNorm (dual output) ----------------------
__global__ __launch_bounds__(256) void ln_residual_kernel(
    const float* __restrict__ a, const float* __restrict__ r,
    const float* __restrict__ g, const float* __restrict__ beta,
    float* __restrict__ out, float* __restrict__ out_r)
{
    __shared__ float red[8];
    const int row = blockIdx.x;
    const int t = threadIdx.x;    // D == 256 threads
    float x = a[(size_t)row * D + t] + r[(size_t)row * D + t];

    float v = x;
#pragma unroll
    for (int o = 16; o > 0; o >>= 1) v += __shfl_down_sync(0xffffffffu, v, o);
    if ((t & 31) == 0) red[t >> 5] = v;
    __syncthreads();
    if (t < 8) {
        float z = red[t];
#pragma unroll
        for (int o = 4; o > 0; o >>= 1) z += __shfl_down_sync(0xffu, z, o);
        if (t == 0) red[0] = z;
    }
    __syncthreads();
    const float mean = red[0] * (1.f / D);
    __syncthreads();

    float d = x - mean;
    v = d * d;
#pragma unroll
    for (int o = 16; o > 0; o >>= 1) v += __shfl_down_sync(0xffffffffu, v, o);
    if ((t & 31) == 0) red[t >> 5] = v;
    __syncthreads();
    if (t < 8) {
        float z = red[t];
#pragma unroll
        for (int o = 4; o > 0; o >>= 1) z += __shfl_down_sync(0xffu, z, o);
        if (t == 0) red[0] = z;
    }
    __syncthreads();
    const float var = red[0] * (1.f / D);

    const float y = d * rsqrtf(var + 1e-5f) * g[t] + beta[t];
    out[(size_t)row * D + t] = y;
    if (out_r) out_r[(size_t)row * D + t] = rnd_tf32(y);
}

// ---------------- host launch ----------------------------------------------
#define SYMPTR(sym) ([]{ void* p = nullptr; cudaGetSymbolAddress(&p, sym); return (float*)p; }())

static inline void mgemm(const float* A, int lda, const float* Bw, int ldb,
                         const float* bias, float* C, int ldc,
                         int M, int N, int K, int relu = 0, int rnd = 0,
                         int cvtA = 0) {
    dim3 grid(N / 128, (M + 127) / 128);
    if (cvtA)
        mma_gemm_kernel<1><<<grid, 256>>>(A, lda, Bw, ldb, bias, C, ldc, M, K, relu, rnd);
    else
        mma_gemm_kernel<0><<<grid, 256>>>(A, lda, Bw, ldb, bias, C, ldc, M, K, relu, rnd);
}

static inline void roundN(const float* in, float* out, int n) {
    int n4 = n / 4;
    round4_kernel<<<(n4 + 255) / 256, 256>>>(in, out, n4);
}

extern "C" void kernel_launch(void* const* d_in, const int* in_sizes, int n_in,
                              void* d_out, int out_size) {
    const float* tgt    = (const float*)d_in[0];
    const float* qpos   = (const float*)d_in[1];
    const float* refpts = (const float*)d_in[2];
    const float* src    = (const float*)d_in[3];
    const float* W_off  = (const float*)d_in[6];
    const float* b_off  = (const float*)d_in[7];
    const float* W_attn = (const float*)d_in[8];
    const float* b_attn = (const float*)d_in[9];
    const float* W_val  = (const float*)d_in[10];
    const float* b_val  = (const float*)d_in[11];
    const float* W_out  = (const float*)d_in[12];
    const float* b_out  = (const float*)d_in[13];
    const float* ln1_g  = (const float*)d_in[14];
    const float* ln1_b  = (const float*)d_in[15];
    const float* inW    = (const float*)d_in[16];
    const float* inB    = (const float*)d_in[17];
    const float* moW    = (const float*)d_in[18];
    const float* moB    = (const float*)d_in[19];
    const float* ln2_g  = (const float*)d_in[20];
    const float* ln2_b  = (const float*)d_in[21];
    const float* W1     = (const float*)d_in[22];
    const float* b1     = (const float*)d_in[23];
    const float* W2     = (const float*)d_in[24];
    const float* b2     = (const float*)d_in[25];
    const float* ln3_g  = (const float*)d_in[26];
    const float* ln3_b  = (const float*)d_in[27];
    float* out = (float*)d_out;

    float* q     = SYMPTR(g_q);
    float* off   = SYMPTR(g_off);
    float* aw    = SYMPTR(g_aw);
    float* val   = SYMPTR(g_val);
    float* msda  = SYMPTR(g_msda);
    float* proj  = SYMPTR(g_proj);
    float* t1    = SYMPTR(g_t1);
    float* t1r   = SYMPTR(g_t1r);
    float* t2    = SYMPTR(g_t2);
    float* t2r   = SYMPTR(g_t2r);
    float* qkv   = SYMPTR(g_qkv);
    float* oatt  = SYMPTR(g_o);
    float* ffn   = SYMPTR(g_ffn);
    float* wr    = SYMPTR(g_wr);

    // rounded weight copies (tf32-rna; GEMM then uses raw bits, zero cvt)
    float* wr_off  = wr + 0;        // 256x256
    float* wr_attn = wr + 65536;    // 128x256
    float* wr_val  = wr + 98304;    // 256x256
    float* wr_out  = wr + 163840;   // 256x256
    float* wr_in   = wr + 229376;   // 768x256
    float* wr_mo   = wr + 425984;   // 256x256
    float* wr_w1   = wr + 491520;   // 1024x256
    float* wr_w2   = wr + 753664;   // 256x1024
    roundN(W_off, wr_off, 65536);
    roundN(W_attn, wr_attn, 32768);
    roundN(W_val, wr_val, 65536);
    roundN(W_out, wr_out, 65536);
    roundN(inW, wr_in, 196608);
    roundN(moW, wr_mo, 65536);
    roundN(W1, wr_w1, 262144);
    roundN(W2, wr_w2, 262144);

    // q = round(tgt + query_pos)
    add_kernel<<<(NQROWS * D + 255) / 256, 256>>>(tgt, qpos, q, NQROWS * D);

    // projections for MSDA  (q rounded -> no cvt; src raw -> cvtA=1)
    mgemm(q, D, wr_off, D, b_off, off, 256, NQROWS, 256, D);
    mgemm(q, D, wr_attn, D, b_attn, aw, 128, NQROWS, 128, D);
    mgemm(src, D, wr_val, D, b_val, val, D, NVROWS, D, D, 0, 0, 1);

    // deformable sampling (output rounded)
    msda_kernel<<<NQROWS, 256>>>(off, aw, refpts, val, msda);

    // output projection + residual LN1
    mgemm(msda, D, wr_out, D, b_out, proj, D, NQROWS, D, D);
    ln_residual_kernel<<<NQROWS, 256>>>(proj, tgt, ln1_g, ln1_b, t1, t1r);

    // self-attention (fused flash attention)
    mgemm(t1r, D, wr_in, D, inB, qkv, 3 * D, NQROWS, 3 * D, D);
    flash_attn_kernel<<<dim3(LQ / 64, BATCH * NH), 128>>>(qkv, oatt);
    mgemm(oatt, D, wr_mo, D, moB, proj, D, NQROWS, D, D);
    ln_residual_kernel<<<NQROWS, 256>>>(proj, t1, ln2_g, ln2_b, t2, t2r);

    // FFN (relu output rounded for next GEMM)
    mgemm(t2r, D, wr_w1, D, b1, ffn, FFD, NQROWS, FFD, D, 1, 1);
    mgemm(ffn, FFD, wr_w2, FFD, b2, proj, D, NQROWS, D, FFD);
    ln_residual_kernel<<<NQROWS, 256>>>(proj, t2, ln3_g, ln3_b, out, nullptr);
}

// round 7
// speedup vs baseline: 1.1032x; 1.1032x over previous
#include <cuda_runtime.h>
#include <cstdint>
#include <math.h>

// Problem constants (fixed by the reference's setup_inputs)
#define D 256
#define FFD 1024
#define NH 8
#define NL 4
#define NP 4
#define HD 32
#define BATCH 8
#define LQ 1024
#define NQROWS (BATCH * LQ)      // 8192
#define LIN 13294
#define NVROWS (BATCH * LIN)     // 106352

__constant__ int c_H[NL]  = {100, 50, 25, 13};
__constant__ int c_W[NL]  = {100, 50, 25, 13};
__constant__ int c_ST[NL] = {0, 10000, 12500, 13125};

// ---------------- scratch (static device memory; no allocations) ----------
__device__ float g_q[NQROWS * D];
__device__ float g_off[NQROWS * D];
__device__ float g_aw[NQROWS * 128];
__device__ float g_val[(size_t)NVROWS * D];
__device__ float g_msda[NQROWS * D];
__device__ float g_proj[NQROWS * D];
__device__ float g_t1[NQROWS * D];
__device__ float g_t2[NQROWS * D];
__device__ float g_qkv[NQROWS * 3 * D];
__device__ float g_o[NQROWS * D];
__device__ float g_ffn[NQROWS * FFD];

// ---------------- elementwise add: q = tgt + query_pos --------------------
__global__ void add_kernel(const float* __restrict__ a, const float* __restrict__ b,
                           float* __restrict__ out, int n) {
    int i = blockIdx.x * blockDim.x + threadIdx.x;
    if (i < n) out[i] = a[i] + b[i];
}

// ======================= common MMA helpers ================================
__device__ __forceinline__ void cp16(uint32_t dst, const float* src, int sz) {
    asm volatile("cp.async.cg.shared.global [%0], [%1], 16, %2;"
                 :: "r"(dst), "l"(src), "r"(sz));
}
__device__ __forceinline__ uint32_t f2tf32(float x) {
    uint32_t r;
    asm("cvt.rna.tf32.f32 %0, %1;" : "=r"(r) : "f"(x));
    return r;
}
__device__ __forceinline__ void mma_tf32(float* d, const uint32_t* a, const uint32_t* b) {
    asm volatile(
        "mma.sync.aligned.m16n8k8.row.col.f32.tf32.tf32.f32 "
        "{%0,%1,%2,%3}, {%4,%5,%6,%7}, {%8,%9}, {%0,%1,%2,%3};"
        : "+f"(d[0]), "+f"(d[1]), "+f"(d[2]), "+f"(d[3])
        : "r"(a[0]), "r"(a[1]), "r"(a[2]), "r"(a[3]), "r"(b[0]), "r"(b[1]));
}

// ======================= tf32 MMA GEMM (BK=32) =============================
// C[M,N] = (A[M,K] @ B[N,K]^T) + bias, optional relu.
// Block tile 128x128, BK=32 double-buffered cp.async, 256 threads (8 warps).
// Requires N % 128 == 0, K % 32 == 0; M guarded.
// Shared memory is DYNAMIC (73728 B > 48 KB static limit).
#define SROW 36   // shared row stride (floats): 36 ≡ 4 (mod 8) -> conflict-free
#define GEMM_SMEM_BYTES (2 * 128 * SROW * 4 * 2)   // A + B, 2 stages = 73728

__global__ __launch_bounds__(256) void mma_gemm_kernel(
    const float* __restrict__ A, int lda,
    const float* __restrict__ Bw, int ldb,
    const float* __restrict__ bias,
    float* __restrict__ C, int ldc,
    int M, int K, int relu)
{
    extern __shared__ float smem[];
    // layout: As[2][128][SROW] then Bs[2][128][SROW]
    float (*As)[128][SROW] = (float (*)[128][SROW])smem;
    float (*Bs)[128][SROW] = (float (*)[128][SROW])(smem + 2 * 128 * SROW);

    const int tid = threadIdx.x;
    const int wid = tid >> 5, lane = tid & 31;
    const int warpM = wid & 1, warpN = wid >> 1;
    const int row0 = blockIdx.y * 128, col0 = blockIdx.x * 128;

    const uint32_t sAbase = (uint32_t)__cvta_generic_to_shared(&As[0][0][0]);
    const uint32_t sBbase = (uint32_t)__cvta_generic_to_shared(&Bs[0][0][0]);

    float acc[4][4][4];
#pragma unroll
    for (int mt = 0; mt < 4; mt++)
#pragma unroll
        for (int nt = 0; nt < 4; nt++)
#pragma unroll
            for (int r = 0; r < 4; r++) acc[mt][nt][r] = 0.f;

    auto load_stage = [&](int k0, int nb) {
        const uint32_t offS = (uint32_t)(nb * 128 * SROW * 4);
#pragma unroll
        for (int i = 0; i < 4; i++) {
            int idx = tid + i * 256;      // 0..1023
            int r = idx >> 3;             // 0..127
            int kq = (idx & 7) * 4;       // 0..28
            int gr = row0 + r;
            const float* gp = A + (size_t)(gr < M ? gr : 0) * lda + k0 + kq;
            cp16(sAbase + offS + (uint32_t)((r * SROW + kq) * 4), gp, gr < M ? 16 : 0);
            const float* bp = Bw + (size_t)(col0 + r) * ldb + k0 + kq;
            cp16(sBbase + offS + (uint32_t)((r * SROW + kq) * 4), bp, 16);
        }
        asm volatile("cp.async.commit_group;");
    };

    load_stage(0, 0);

    const int KT = K >> 5;
    for (int kt = 0; kt < KT; kt++) {
        const int buf = kt & 1;
        if (kt + 1 < KT) {
            load_stage((kt + 1) << 5, buf ^ 1);
            asm volatile("cp.async.wait_group 1;");
        } else {
            asm volatile("cp.async.wait_group 0;");
        }
        __syncthreads();

#pragma unroll
        for (int ks = 0; ks < 4; ks++) {
            uint32_t af[4][4], bf[4][2];
            const int kc = ks * 8 + (lane & 3);
            const int g4 = lane >> 2;
#pragma unroll
            for (int mt = 0; mt < 4; mt++) {
                const int r = warpM * 64 + mt * 16 + g4;
                af[mt][0] = f2tf32(As[buf][r][kc]);
                af[mt][1] = f2tf32(As[buf][r + 8][kc]);
                af[mt][2] = f2tf32(As[buf][r][kc + 4]);
                af[mt][3] = f2tf32(As[buf][r + 8][kc + 4]);
            }
#pragma unroll
            for (int nt = 0; nt < 4; nt++) {
                const int n = warpN * 32 + nt * 8 + g4;
                bf[nt][0] = f2tf32(Bs[buf][n][kc]);
                bf[nt][1] = f2tf32(Bs[buf][n][kc + 4]);
            }
#pragma unroll
            for (int mt = 0; mt < 4; mt++)
#pragma unroll
                for (int nt = 0; nt < 4; nt++)
                    mma_tf32(acc[mt][nt], af[mt], bf[nt]);
        }
        __syncthreads();
    }

    const int g4 = lane >> 2;
    const int c2 = (lane & 3) * 2;
#pragma unroll
    for (int mt = 0; mt < 4; mt++) {
        const int r = row0 + warpM * 64 + mt * 16 + g4;
#pragma unroll
        for (int nt = 0; nt < 4; nt++) {
            const int cc = col0 + warpN * 32 + nt * 8 + c2;
            float b0 = 0.f, b1 = 0.f;
            if (bias) { b0 = bias[cc]; b1 = bias[cc + 1]; }
            float v0 = acc[mt][nt][0] + b0;
            float v1 = acc[mt][nt][1] + b1;
            float v2 = acc[mt][nt][2] + b0;
            float v3 = acc[mt][nt][3] + b1;
            if (relu) {
                v0 = fmaxf(v0, 0.f); v1 = fmaxf(v1, 0.f);
                v2 = fmaxf(v2, 0.f); v3 = fmaxf(v3, 0.f);
            }
            if (r < M)     *(float2*)(C + (size_t)r * ldc + cc)       = make_float2(v0, v1);
            if (r + 8 < M) *(float2*)(C + (size_t)(r + 8) * ldc + cc) = make_float2(v2, v3);
        }
    }
}

// ======================= flash attention (double-buffered K/V) =============
// Per block: one (b,h) and a 64-query tile. 128 threads = 4 warps (2x2).
// Static smem: 64*36 + 2*64*36 + 2*64*40 + 2*64*2 floats = 48,128 B? Let's count:
//   Qs 64*36*4 = 9216; Ks 2*64*36*4 = 18432; Vs 2*64*40*4 = 20480; rm/rl 2*2*64*4 = 2048
//   total = 50176 B > 49152 static limit -> use dynamic smem here too.
#define FLASH_SMEM_BYTES (9216 + 18432 + 20480 + 2048)   // 50176

__global__ __launch_bounds__(128) void flash_attn_kernel(
    const float* __restrict__ qkv, float* __restrict__ o)
{
    extern __shared__ float fsm[];
    float (*Qs)[36]     = (float (*)[36])fsm;                       // [64][36]
    float (*Ks)[64][36] = (float (*)[64][36])(fsm + 64 * 36);       // [2][64][36]
    float (*Vs)[64][40] = (float (*)[64][40])(fsm + 64 * 36 + 2 * 64 * 36); // [2][64][40]
    float (*rm)[64]     = (float (*)[64])(fsm + 64 * 36 + 2 * 64 * 36 + 2 * 64 * 40);
    float (*rl)[64]     = (float (*)[64])((float*)rm + 2 * 64);

    const int bh = blockIdx.y;
    const int b = bh >> 3, h = bh & 7;
    const int q0 = blockIdx.x * 64;
    const int tid = threadIdx.x;
    const int wid = tid >> 5, lane = tid & 31;
    const int warpM = wid & 1, warpN = wid >> 1;
    const int g4 = lane >> 2, l3 = lane & 3;
    const float scale = 0.17677669529663687f;   // 1/sqrt(32)

    const uint32_t sK = (uint32_t)__cvta_generic_to_shared(&Ks[0][0][0]);
    const uint32_t sV = (uint32_t)__cvta_generic_to_shared(&Vs[0][0][0]);

    auto load_kv = [&](int kt, int nb) {
        const int k0 = kt * 64;
        const uint32_t offK = (uint32_t)(nb * 64 * 36 * 4);
        const uint32_t offV = (uint32_t)(nb * 64 * 40 * 4);
#pragma unroll
        for (int i = 0; i < 4; i++) {
            int idx = tid + i * 128;
            int r = idx >> 3, cq = (idx & 7) * 4;
            const float* kp = qkv + ((size_t)(b * LQ + k0 + r)) * 768 + 256 + h * 32 + cq;
            cp16(sK + offK + (uint32_t)((r * 36 + cq) * 4), kp, 16);
            const float* vp = qkv + ((size_t)(b * LQ + k0 + r)) * 768 + 512 + h * 32 + cq;
            cp16(sV + offV + (uint32_t)((r * 40 + cq) * 4), vp, 16);
        }
        asm volatile("cp.async.commit_group;");
    };

    // ---- load Q tile (64x32) ----
#pragma unroll
    for (int i = 0; i < 4; i++) {
        int idx = tid + i * 128;               // 0..511
        int r = idx >> 3, cq = (idx & 7) * 4;
        float4 f = *(const float4*)(qkv + ((size_t)(b * LQ + q0 + r)) * 768 + h * 32 + cq);
        Qs[r][cq + 0] = f.x; Qs[r][cq + 1] = f.y;
        Qs[r][cq + 2] = f.z; Qs[r][cq + 3] = f.w;
    }
    load_kv(0, 0);
    __syncthreads();

    // ---- preload Q fragments (scaled, tf32) ----
    uint32_t qf[2][4][4];
#pragma unroll
    for (int mt = 0; mt < 2; mt++) {
        const int r0 = warpM * 32 + mt * 16 + g4;
#pragma unroll
        for (int ks = 0; ks < 4; ks++) {
            const int k = ks * 8 + l3;
            qf[mt][ks][0] = f2tf32(Qs[r0][k] * scale);
            qf[mt][ks][1] = f2tf32(Qs[r0 + 8][k] * scale);
            qf[mt][ks][2] = f2tf32(Qs[r0][k + 4] * scale);
            qf[mt][ks][3] = f2tf32(Qs[r0 + 8][k + 4] * scale);
        }
    }
    __syncthreads();                            // Qs now reusable as P
    uint32_t* Ps = (uint32_t*)&Qs[0][0];        // [64][36]

    float Oa[2][2][4];
#pragma unroll
    for (int mt = 0; mt < 2; mt++)
#pragma unroll
        for (int nt = 0; nt < 2; nt++)
#pragma unroll
            for (int r = 0; r < 4; r++) Oa[mt][nt][r] = 0.f;
    float m_r[2][2], l_r[2][2];
#pragma unroll
    for (int mt = 0; mt < 2; mt++) {
        m_r[mt][0] = -1e30f; m_r[mt][1] = -1e30f;
        l_r[mt][0] = 0.f;    l_r[mt][1] = 0.f;
    }

    for (int kt = 0; kt < 16; kt++) {
        const int buf = kt & 1;
        if (kt + 1 < 16) {
            load_kv(kt + 1, buf ^ 1);
            asm volatile("cp.async.wait_group 1;");
        } else {
            asm volatile("cp.async.wait_group 0;");
        }
        __syncthreads();

        // ---- S = Q @ K^T  (64x64, warp tile 32x32) ----
        float Sa[2][4][4];
#pragma unroll
        for (int mt = 0; mt < 2; mt++)
#pragma unroll
            for (int nt = 0; nt < 4; nt++)
#pragma unroll
                for (int r = 0; r < 4; r++) Sa[mt][nt][r] = 0.f;
#pragma unroll
        for (int ks = 0; ks < 4; ks++) {
            uint32_t bf[4][2];
            const int k = ks * 8 + l3;
#pragma unroll
            for (int nt = 0; nt < 4; nt++) {
                const int n = warpN * 32 + nt * 8 + g4;
                bf[nt][0] = f2tf32(Ks[buf][n][k]);
                bf[nt][1] = f2tf32(Ks[buf][n][k + 4]);
            }
#pragma unroll
            for (int mt = 0; mt < 2; mt++)
#pragma unroll
                for (int nt = 0; nt < 4; nt++)
                    mma_tf32(Sa[mt][nt], qf[mt][ks], bf[nt]);
        }

        // ---- per-warp row max ----
#pragma unroll
        for (int mt = 0; mt < 2; mt++) {
            float m0 = -1e30f, m1 = -1e30f;
#pragma unroll
            for (int nt = 0; nt < 4; nt++) {
                m0 = fmaxf(m0, fmaxf(Sa[mt][nt][0], Sa[mt][nt][1]));
                m1 = fmaxf(m1, fmaxf(Sa[mt][nt][2], Sa[mt][nt][3]));
            }
            m0 = fmaxf(m0, __shfl_xor_sync(0xffffffffu, m0, 1));
            m0 = fmaxf(m0, __shfl_xor_sync(0xffffffffu, m0, 2));
            m1 = fmaxf(m1, __shfl_xor_sync(0xffffffffu, m1, 1));
            m1 = fmaxf(m1, __shfl_xor_sync(0xffffffffu, m1, 2));
            if (l3 == 0) {
                rm[warpN][warpM * 32 + mt * 16 + g4] = m0;
                rm[warpN][warpM * 32 + mt * 16 + g4 + 8] = m1;
            }
        }
        __syncthreads();

        // ---- exp, P -> smem, partial row sums ----
        float mn[2][2];
#pragma unroll
        for (int mt = 0; mt < 2; mt++) {
            const int r0 = warpM * 32 + mt * 16 + g4;
            mn[mt][0] = fmaxf(m_r[mt][0], fmaxf(rm[0][r0], rm[1][r0]));
            mn[mt][1] = fmaxf(m_r[mt][1], fmaxf(rm[0][r0 + 8], rm[1][r0 + 8]));
            float s0 = 0.f, s1 = 0.f;
#pragma unroll
            for (int nt = 0; nt < 4; nt++) {
                float p0 = __expf(Sa[mt][nt][0] - mn[mt][0]);
                float p1 = __expf(Sa[mt][nt][1] - mn[mt][0]);
                float p2 = __expf(Sa[mt][nt][2] - mn[mt][1]);
                float p3 = __expf(Sa[mt][nt][3] - mn[mt][1]);
                s0 += p0 + p1; s1 += p2 + p3;
                const int cc = warpN * 32 + nt * 8 + l3 * 2;
                Ps[r0 * 36 + cc]           = f2tf32(p0);
                Ps[r0 * 36 + cc + 1]       = f2tf32(p1);
                Ps[(r0 + 8) * 36 + cc]     = f2tf32(p2);
                Ps[(r0 + 8) * 36 + cc + 1] = f2tf32(p3);
            }
            s0 += __shfl_xor_sync(0xffffffffu, s0, 1);
            s0 += __shfl_xor_sync(0xffffffffu, s0, 2);
            s1 += __shfl_xor_sync(0xffffffffu, s1, 1);
            s1 += __shfl_xor_sync(0xffffffffu, s1, 2);
            if (l3 == 0) {
                rl[warpN][r0] = s0;
                rl[warpN][r0 + 8] = s1;
            }
        }
        __syncthreads();

        // ---- rescale O, update m/l ----
#pragma unroll
        for (int mt = 0; mt < 2; mt++) {
            const int r0 = warpM * 32 + mt * 16 + g4;
            const float a0 = __expf(m_r[mt][0] - mn[mt][0]);
            const float a1 = __expf(m_r[mt][1] - mn[mt][1]);
            l_r[mt][0] = l_r[mt][0] * a0 + rl[0][r0] + rl[1][r0];
            l_r[mt][1] = l_r[mt][1] * a1 + rl[0][r0 + 8] + rl[1][r0 + 8];
            m_r[mt][0] = mn[mt][0];
            m_r[mt][1] = mn[mt][1];
#pragma unroll
            for (int nt = 0; nt < 2; nt++) {
                Oa[mt][nt][0] *= a0; Oa[mt][nt][1] *= a0;
                Oa[mt][nt][2] *= a1; Oa[mt][nt][3] *= a1;
            }
        }

        // ---- O += P @ V  (64x32, warp tile 32x16) ----
#pragma unroll
        for (int kk = 0; kk < 8; kk++) {
            const int k = kk * 8 + l3;
            uint32_t bf[2][2];
#pragma unroll
            for (int nt = 0; nt < 2; nt++) {
                const int n = warpN * 16 + nt * 8 + g4;
                bf[nt][0] = f2tf32(Vs[buf][k][n]);
                bf[nt][1] = f2tf32(Vs[buf][k + 4][n]);
            }
#pragma unroll
            for (int mt = 0; mt < 2; mt++) {
                const int r0 = warpM * 32 + mt * 16 + g4;
                uint32_t af[4];
                af[0] = Ps[r0 * 36 + k];
                af[1] = Ps[(r0 + 8) * 36 + k];
                af[2] = Ps[r0 * 36 + k + 4];
                af[3] = Ps[(r0 + 8) * 36 + k + 4];
#pragma unroll
                for (int nt = 0; nt < 2; nt++)
                    mma_tf32(Oa[mt][nt], af, bf[nt]);
            }
        }
        __syncthreads();
    }

    // ---- finalize: O /= l, write out ----
    const int c2 = l3 * 2;
#pragma unroll
    for (int mt = 0; mt < 2; mt++) {
        const int r0 = q0 + warpM * 32 + mt * 16 + g4;
        const float i0 = 1.f / l_r[mt][0];
        const float i1 = 1.f / l_r[mt][1];
#pragma unroll
        for (int nt = 0; nt < 2; nt++) {
            const int cc = h * 32 + warpN * 16 + nt * 8 + c2;
            *(float2*)(o + ((size_t)(b * LQ + r0)) * D + cc) =
                make_float2(Oa[mt][nt][0] * i0, Oa[mt][nt][1] * i0);
            *(float2*)(o + ((size_t)(b * LQ + r0 + 8)) * D + cc) =
                make_float2(Oa[mt][nt][2] * i1, Oa[mt][nt][3] * i1);
        }
    }
}

// ---------------- MSDA sampling kernel ------------------------------------
__global__ __launch_bounds__(256) void msda_kernel(
    const float* __restrict__ off, const float* __restrict__ awraw,
    const float* __restrict__ ref, const float* __restrict__ val,
    float* __restrict__ out)
{
    const int row = blockIdx.x;            // b*LQ + lq
    const int b = row >> 10;
    const int t = threadIdx.x;
    const int h = t >> 5;
    const int c = t & 31;

    const float* awp = awraw + (size_t)row * 128 + h * 16;
    float w[16];
    float mx = -1e30f;
#pragma unroll
    for (int i = 0; i < 16; i++) { w[i] = awp[i]; mx = fmaxf(mx, w[i]); }
    float s = 0.f;
#pragma unroll
    for (int i = 0; i < 16; i++) { w[i] = expf(w[i] - mx); s += w[i]; }
    const float inv = 1.f / s;

    const float* offp = off + (size_t)row * 256 + h * 32;   // [NL][NP][2]
    const float* refp = ref + (size_t)row * (NL * 2);

    float acc = 0.f;
#pragma unroll
    for (int l = 0; l < NL; l++) {
        const float rx = refp[l * 2 + 0];
        const float ry = refp[l * 2 + 1];
        const int H = c_H[l], W = c_W[l];
        const float fW = (float)W, fH = (float)H;
        const float* vbase = val + ((size_t)b * LIN + c_ST[l]) * D + h * HD + c;
#pragma unroll
        for (int p = 0; p < NP; p++) {
            const float ox = offp[(l * NP + p) * 2 + 0];
            const float oy = offp[(l * NP + p) * 2 + 1];
            const float x = (rx + ox / fW) * fW - 0.5f;
            const float y = (ry + oy / fH) * fH - 0.5f;
            const float x0f = floorf(x), y0f = floorf(y);
            const float wx = x - x0f, wy = y - y0f;
            const int x0 = (int)x0f, y0 = (int)y0f;
            float samp = 0.f;
            if (y0 >= 0 && y0 < H) {
                if (x0 >= 0 && x0 < W)
                    samp += (1.f - wy) * (1.f - wx) * vbase[(size_t)(y0 * W + x0) * D];
                if (x0 + 1 >= 0 && x0 + 1 < W)
                    samp += (1.f - wy) * wx * vbase[(size_t)(y0 * W + x0 + 1) * D];
            }
            if (y0 + 1 >= 0 && y0 + 1 < H) {
                if (x0 >= 0 && x0 < W)
                    samp += wy * (1.f - wx) * vbase[(size_t)((y0 + 1) * W + x0) * D];
                if (x0 + 1 >= 0 && x0 + 1 < W)
                    samp += wy * wx * vbase[(size_t)((y0 + 1) * W + x0 + 1) * D];
            }
            acc = fmaf(w[l * NP + p] * inv, samp, acc);
        }
    }
    out[(size_t)row * D + h * HD + c] = acc;
}

// ---------------- residual + LayerNorm ------------------------------------
__global__ __launch_bounds__(256) void ln_residual_kernel(
    const float* __restrict__ a, const float* __restrict__ r,
    const float* __restrict__ g, const float* __restrict__ beta,
    float* __restrict__ out)
{
    __shared__ float red[8];
    const int row = blockIdx.x;
    const int t = threadIdx.x;    // D == 256 threads
    float x = a[(size_t)row * D + t] + r[(size_t)row * D + t];

    float v = x;
#pragma unroll
    for (int o = 16; o > 0; o >>= 1) v += __shfl_down_sync(0xffffffffu, v, o);
    if ((t & 31) == 0) red[t >> 5] = v;
    __syncthreads();
    if (t < 8) {
        float z = red[t];
#pragma unroll
        for (int o = 4; o > 0; o >>= 1) z += __shfl_down_sync(0xffu, z, o);
        if (t == 0) red[0] = z;
    }
    __syncthreads();
    const float mean = red[0] * (1.f / D);
    __syncthreads();

    float d = x - mean;
    v = d * d;
#pragma unroll
    for (int o = 16; o > 0; o >>= 1) v += __shfl_down_sync(0xffffffffu, v, o);
    if ((t & 31) == 0) red[t >> 5] = v;
    __syncthreads();
    if (t < 8) {
        float z = red[t];
#pragma unroll
        for (int o = 4; o > 0; o >>= 1) z += __shfl_down_sync(0xffu, z, o);
        if (t == 0) red[0] = z;
    }
    __syncthreads();
    const float var = red[0] * (1.f / D);

    out[(size_t)row * D + t] = d * rsqrtf(var + 1e-5f) * g[t] + beta[t];
}

// ---------------- host launch ----------------------------------------------
#define SYMPTR(sym) ([]{ void* p = nullptr; cudaGetSymbolAddress(&p, sym); return (float*)p; }())

static inline void mgemm(const float* A, int lda, const float* Bw, int ldb,
                         const float* bias, float* C, int ldc,
                         int M, int N, int K, int relu = 0) {
    dim3 grid(N / 128, (M + 127) / 128);
    mma_gemm_kernel<<<grid, 256, GEMM_SMEM_BYTES>>>(A, lda, Bw, ldb, bias, C, ldc, M, K, relu);
}

extern "C" void kernel_launch(void* const* d_in, const int* in_sizes, int n_in,
                              void* d_out, int out_size) {
    const float* tgt    = (const float*)d_in[0];
    const float* qpos   = (const float*)d_in[1];
    const float* refpts = (const float*)d_in[2];
    const float* src    = (const float*)d_in[3];
    const float* W_off  = (const float*)d_in[6];
    const float* b_off  = (const float*)d_in[7];
    const float* W_attn = (const float*)d_in[8];
    const float* b_attn = (const float*)d_in[9];
    const float* W_val  = (const float*)d_in[10];
    const float* b_val  = (const float*)d_in[11];
    const float* W_out  = (const float*)d_in[12];
    const float* b_out  = (const float*)d_in[13];
    const float* ln1_g  = (const float*)d_in[14];
    const float* ln1_b  = (const float*)d_in[15];
    const float* inW    = (const float*)d_in[16];
    const float* inB    = (const float*)d_in[17];
    const float* moW    = (const float*)d_in[18];
    const float* moB    = (const float*)d_in[19];
    const float* ln2_g  = (const float*)d_in[20];
    const float* ln2_b  = (const float*)d_in[21];
    const float* W1     = (const float*)d_in[22];
    const float* b1     = (const float*)d_in[23];
    const float* W2     = (const float*)d_in[24];
    const float* b2     = (const float*)d_in[25];
    const float* ln3_g  = (const float*)d_in[26];
    const float* ln3_b  = (const float*)d_in[27];
    float* out = (float*)d_out;

    static int configured = 0;
    if (!configured) {
        cudaFuncSetAttribute(mma_gemm_kernel,
                             cudaFuncAttributeMaxDynamicSharedMemorySize, GEMM_SMEM_BYTES);
        cudaFuncSetAttribute(flash_attn_kernel,
                             cudaFuncAttributeMaxDynamicSharedMemorySize, FLASH_SMEM_BYTES);
        configured = 1;
    }

    float* q     = SYMPTR(g_q);
    float* off   = SYMPTR(g_off);
    float* aw    = SYMPTR(g_aw);
    float* val   = SYMPTR(g_val);
    float* msda  = SYMPTR(g_msda);
    float* proj  = SYMPTR(g_proj);
    float* t1    = SYMPTR(g_t1);
    float* t2    = SYMPTR(g_t2);
    float* qkv   = SYMPTR(g_qkv);
    float* oatt  = SYMPTR(g_o);
    float* ffn   = SYMPTR(g_ffn);

    // q = tgt + query_pos
    add_kernel<<<(NQROWS * D + 255) / 256, 256>>>(tgt, qpos, q, NQROWS * D);

    // projections for MSDA
    mgemm(q, D, W_off, D, b_off, off, 256, NQROWS, 256, D);
    mgemm(q, D, W_attn, D, b_attn, aw, 128, NQROWS, 128, D);
    mgemm(src, D, W_val, D, b_val, val, D, NVROWS, D, D);

    // deformable sampling
    msda_kernel<<<NQROWS, 256>>>(off, aw, refpts, val, msda);

    // output projection + residual LN1
    mgemm(msda, D, W_out, D, b_out, proj, D, NQROWS, D, D);
    ln_residual_kernel<<<NQROWS, 256>>>(proj, tgt, ln1_g, ln1_b, t1);

    // self-attention (fused flash attention)
    mgemm(t1, D, inW, D, inB, qkv, 3 * D, NQROWS, 3 * D, D);
    flash_attn_kernel<<<dim3(LQ / 64, BATCH * NH), 128, FLASH_SMEM_BYTES>>>(qkv, oatt);
    mgemm(oatt, D, moW, D, moB, proj, D, NQROWS, D, D);
    ln_residual_kernel<<<NQROWS, 256>>>(proj, t1, ln2_g, ln2_b, t2);

    // FFN
    mgemm(t2, D, W1, D, b1, ffn, FFD, NQROWS, FFD, D, 1);
    mgemm(ffn, FFD, W2, FFD, b2, proj, D, NQROWS, D, FFD);
    ln_residual_kernel<<<NQROWS, 256>>>(proj, t2, ln3_g, ln3_b, out);
}